// round 3
// baseline (speedup 1.0000x reference)
#include <cuda_runtime.h>
#include <cstdint>
#include <cfloat>
#include <math.h>

#define DIMS 768
#define TM 128
#define TN 64
#define TK 32
#define MAX_M 500000
#define MAX_N 256

// Scratch (allocation-free rule: use __device__ globals)
__device__ float g_scores[(size_t)MAX_N * MAX_M];         // 512 MB scores
__device__ float g_dbn[(size_t)MAX_M * DIMS];             // 1.536 GB normalized db
__device__ float g_qn[(size_t)MAX_N * DIMS];              // normalized queries

// ---------------------------------------------------------------------------
// L2-normalize rows, mimicking XLA fp32 semantics as closely as possible:
//  - warp per row
//  - lane-strided scalar loads x[lane + 32*i], i ascending
//  - per-lane sequential fmaf(v, v, s) accumulation
//  - warp shuffle tree reduce (same pairing as shfl_down tree at lane 0)
//  - norm = sqrtf(sum); denom = max(norm, 1e-12f); y = x / denom  (IEEE div)
// ---------------------------------------------------------------------------
__global__ void normalize_kernel(const float* __restrict__ x,
                                 float* __restrict__ y, int rows)
{
    int warp = (blockIdx.x * blockDim.x + threadIdx.x) >> 5;
    int lane = threadIdx.x & 31;
    if (warp >= rows) return;
    const float* r = x + (size_t)warp * DIMS;
    float s = 0.0f;
#pragma unroll
    for (int i = 0; i < DIMS / 32; i++) {       // 24 scalar elems per lane, ascending
        float v = r[lane + 32 * i];
        s = fmaf(v, v, s);
    }
#pragma unroll
    for (int o = 16; o; o >>= 1) s += __shfl_xor_sync(0xffffffffu, s, o);
    float denom = fmaxf(sqrtf(s), 1e-12f);
    denom = __shfl_sync(0xffffffffu, denom, 0); // lane 0's bits everywhere

    float* w = y + (size_t)warp * DIMS;
#pragma unroll
    for (int i = 0; i < DIMS / 32; i++) {
        float v = r[lane + 32 * i];
        w[lane + 32 * i] = v / denom;           // correctly-rounded div (prec-div)
    }
}

// ---------------------------------------------------------------------------
// fp32 SGEMM (NT): C[i][j] = sum_k A[i][k]*B[j][k] on pre-normalized inputs.
// Single fp32 accumulator per output, one FMA per k, k strictly ascending ->
// bit-identical to any other sequential fp32 FMA chain (e.g. cublas sgemm).
// Tile 128x64x32, 256 threads, 8x4 micro-tile, double-buffered smem.
// ---------------------------------------------------------------------------
__global__ void __launch_bounds__(256, 2)
gemm_kernel(const float* __restrict__ A, const float* __restrict__ B,
            int NQ, int Mdb)
{
    __shared__ float As[2][TK][TM];
    __shared__ float Bs[2][TK][TN];

    const int t  = threadIdx.x;
    const int tx = t & 15;
    const int ty = t >> 4;
    const int rowBase = blockIdx.y * TM;
    const int colBase = blockIdx.x * TN;

    float acc[8][4];
#pragma unroll
    for (int i = 0; i < 8; i++)
#pragma unroll
        for (int j = 0; j < 4; j++) acc[i][j] = 0.0f;

    float4 aReg[4];
    float4 bReg[2];
    const int nChunks = DIMS / TK;    // 24

    auto loadA = [&](int chunk) {
#pragma unroll
        for (int i = 0; i < 4; i++) {
            int f  = t + 256 * i;
            int m  = f >> 3;
            int kq = (f & 7) << 2;
            int row = rowBase + m; if (row > NQ - 1) row = NQ - 1;
            aReg[i] = *(const float4*)(A + (size_t)row * DIMS + chunk * TK + kq);
        }
    };
    auto loadB = [&](int chunk) {
#pragma unroll
        for (int i = 0; i < 2; i++) {
            int f  = t + 256 * i;
            int n  = f >> 3;
            int kq = (f & 7) << 2;
            int col = colBase + n;
            if (col < Mdb)
                bReg[i] = *(const float4*)(B + (size_t)col * DIMS + chunk * TK + kq);
            else
                bReg[i] = make_float4(0.f, 0.f, 0.f, 0.f);
        }
    };
    auto stage = [&](int buf) {
#pragma unroll
        for (int i = 0; i < 4; i++) {
            int f  = t + 256 * i;
            int m  = f >> 3;
            int kq = (f & 7) << 2;
            const float* pv = (const float*)&aReg[i];
#pragma unroll
            for (int c = 0; c < 4; c++) As[buf][kq + c][m] = pv[c];
        }
#pragma unroll
        for (int i = 0; i < 2; i++) {
            int f  = t + 256 * i;
            int n  = f >> 3;
            int kq = (f & 7) << 2;
            const float* pv = (const float*)&bReg[i];
#pragma unroll
            for (int c = 0; c < 4; c++) Bs[buf][kq + c][n] = pv[c];
        }
    };

    loadA(0); loadB(0);
    stage(0);
    __syncthreads();

    for (int c = 0; c < nChunks; c++) {
        int buf = c & 1;
        if (c + 1 < nChunks) { loadA(c + 1); loadB(c + 1); }

#pragma unroll
        for (int kk = 0; kk < TK; kk++) {
            float a[8], b[4];
            *(float4*)&a[0] = *(const float4*)&As[buf][kk][ty * 8];
            *(float4*)&a[4] = *(const float4*)&As[buf][kk][ty * 8 + 4];
            *(float4*)&b[0] = *(const float4*)&Bs[buf][kk][tx * 4];
#pragma unroll
            for (int i = 0; i < 8; i++)
#pragma unroll
                for (int j = 0; j < 4; j++)
                    acc[i][j] = fmaf(a[i], b[j], acc[i][j]);
        }

        if (c + 1 < nChunks) stage(buf ^ 1);
        __syncthreads();
    }

    // Epilogue: write raw dot products (inputs already normalized)
    int col0 = colBase + tx * 4;
    bool fast = (col0 + 3 < Mdb) && (rowBase + TM <= NQ);
    if (fast) {
#pragma unroll
        for (int i = 0; i < 8; i++) {
            int row = rowBase + ty * 8 + i;
            *(float4*)(g_scores + (size_t)row * Mdb + col0) = *(float4*)&acc[i][0];
        }
    } else {
#pragma unroll
        for (int j = 0; j < 4; j++) {
            int col = col0 + j;
            if (col >= Mdb) continue;
#pragma unroll
            for (int i = 0; i < 8; i++) {
                int row = rowBase + ty * 8 + i;
                if (row < NQ)
                    g_scores[(size_t)row * Mdb + col] = acc[i][j];
            }
        }
    }
}

// ---------------------------------------------------------------------------
// Top-16 per query. One block per query row. Each thread keeps a sorted
// local top-16 (score desc, tie -> smaller index, matching jax.lax.top_k),
// then 16 rounds of block-wide argmax extraction.
// Output layout: out[0 .. NQ*16)          = top scores
//                out[NQ*16 .. 2*NQ*16)    = top indices (as float)
// ---------------------------------------------------------------------------
__global__ void __launch_bounds__(512)
topk_kernel(float* __restrict__ out, int NQ, int Mdb)
{
    const int q    = blockIdx.x;
    const int t    = threadIdx.x;
    const int lane = t & 31;
    const int wid  = t >> 5;
    const float* row = g_scores + (size_t)q * Mdb;

    float val[16];
    int   idx[16];
#pragma unroll
    for (int i = 0; i < 16; i++) { val[i] = -FLT_MAX; idx[i] = 0x7fffffff; }
    float vmin = -FLT_MAX;

    auto consider = [&](float s, int j) {
        bool take = (s > vmin) || (s == vmin && j < idx[15]);
        if (take) {
            int p = 15;
            while (p > 0 && (val[p - 1] < s || (val[p - 1] == s && idx[p - 1] > j))) {
                val[p] = val[p - 1]; idx[p] = idx[p - 1]; --p;
            }
            val[p] = s; idx[p] = j;
            vmin = val[15];
        }
    };

    if ((Mdb & 3) == 0) {
        const float4* r4 = (const float4*)row;
        int nf4 = Mdb >> 2;
        for (int f = t; f < nf4; f += 512) {
            float4 v = r4[f];
            int j = f << 2;
            consider(v.x, j);
            consider(v.y, j + 1);
            consider(v.z, j + 2);
            consider(v.w, j + 3);
        }
    } else {
        for (int j = t; j < Mdb; j += 512) consider(row[j], j);
    }

    __shared__ float sv[16];
    __shared__ int   si[16];
    __shared__ int   st[16];
    __shared__ int   wt;

    int pos = 0;
    for (int r = 0; r < 16; r++) {
        float v  = (pos < 16) ? val[pos] : -FLT_MAX;
        int   ii = (pos < 16) ? idx[pos] : 0x7fffffff;
        int   tt = t;
#pragma unroll
        for (int o = 16; o; o >>= 1) {
            float v2 = __shfl_xor_sync(0xffffffffu, v, o);
            int   i2 = __shfl_xor_sync(0xffffffffu, ii, o);
            int   t2 = __shfl_xor_sync(0xffffffffu, tt, o);
            if (v2 > v || (v2 == v && i2 < ii)) { v = v2; ii = i2; tt = t2; }
        }
        if (lane == 0) { sv[wid] = v; si[wid] = ii; st[wid] = tt; }
        __syncthreads();
        if (t == 0) {
            float bv = sv[0]; int bi = si[0]; int bt = st[0];
#pragma unroll
            for (int w = 1; w < 16; w++)
                if (sv[w] > bv || (sv[w] == bv && si[w] < bi)) {
                    bv = sv[w]; bi = si[w]; bt = st[w];
                }
            wt = bt;
            out[q * 16 + r]           = bv;
            out[NQ * 16 + q * 16 + r] = (float)bi;
        }
        __syncthreads();
        if (t == wt) pos++;
    }
}

// ---------------------------------------------------------------------------
extern "C" void kernel_launch(void* const* d_in, const int* in_sizes, int n_in,
                              void* d_out, int out_size)
{
    const float* q  = (const float*)d_in[0];
    const float* db = (const float*)d_in[1];
    int NQ  = in_sizes[0] / DIMS;   // 256
    int Mdb = in_sizes[1] / DIMS;   // 500000
    if (NQ > MAX_N) NQ = MAX_N;
    if (Mdb > MAX_M) Mdb = MAX_M;
    float* out = (float*)d_out;

    // Pointers to __device__ globals (host-side symbol addresses resolve at
    // module scope; pass via kernel args by taking device address in a kernel
    // is unnecessary — __device__ arrays are directly addressable in kernels).
    normalize_kernel<<<(Mdb + 7) / 8, 256>>>(db, g_dbn, Mdb);
    normalize_kernel<<<(NQ + 7) / 8, 256>>>(q, g_qn, NQ);

    dim3 grid((Mdb + TN - 1) / TN, (NQ + TM - 1) / TM);
    gemm_kernel<<<grid, 256>>>(g_qn, g_dbn, NQ, Mdb);

    topk_kernel<<<NQ, 512>>>(out, NQ, Mdb);
}

// round 5
// speedup vs baseline: 1.2328x; 1.2328x over previous
#include <cuda_runtime.h>
#include <cstdint>
#include <cfloat>
#include <math.h>

#define DIMS 768
#define TM 128
#define TN 128
#define TK 16
#define SPAD 132            // row pitch (floats): multiple of 4 (float4-aligned LDS),
                            // kq*132 mod 32 alternates 0/16 -> at worst 2-way STS conflict
#define MAX_M 500000
#define MAX_N 256

// Scratch (allocation-free rule: use __device__ globals)
__device__ float g_scores[(size_t)MAX_N * MAX_M];         // 512 MB scores
__device__ float g_dbn[(size_t)MAX_M * DIMS];             // normalized db
__device__ float g_qn[(size_t)MAX_N * DIMS];              // normalized queries

// ---------------------------------------------------------------------------
// L2-normalize rows (UNCHANGED from passing R2 kernel — bit-identical output)
// ---------------------------------------------------------------------------
__global__ void normalize_kernel(const float* __restrict__ x,
                                 float* __restrict__ y, int rows)
{
    int warp = (blockIdx.x * blockDim.x + threadIdx.x) >> 5;
    int lane = threadIdx.x & 31;
    if (warp >= rows) return;
    const float* r = x + (size_t)warp * DIMS;
    float s = 0.0f;
#pragma unroll
    for (int i = 0; i < DIMS / 32; i++) {
        float v = r[lane + 32 * i];
        s = fmaf(v, v, s);
    }
#pragma unroll
    for (int o = 16; o; o >>= 1) s += __shfl_xor_sync(0xffffffffu, s, o);
    float denom = fmaxf(sqrtf(s), 1e-12f);
    denom = __shfl_sync(0xffffffffu, denom, 0);

    float* w = y + (size_t)warp * DIMS;
#pragma unroll
    for (int i = 0; i < DIMS / 32; i++) {
        float v = r[lane + 32 * i];
        w[lane + 32 * i] = v / denom;
    }
}

// ---------------------------------------------------------------------------
// fp32 SGEMM (NT): C[i][j] = sum_k A[i][k]*B[j][k] on normalized inputs.
// 128x128x16 tile, 256 threads, 8x8 micro-tile, double-buffered k-major smem.
// Accumulation: ONE fp32 FMA per k, k strictly ascending -> bit-identical
// scores to the passing R2 kernel.
// ---------------------------------------------------------------------------
__global__ void __launch_bounds__(256, 2)
gemm_kernel(const float* __restrict__ A, const float* __restrict__ B,
            int NQ, int Mdb)
{
    __shared__ float As[2][TK][SPAD];
    __shared__ float Bs[2][TK][SPAD];

    const int t  = threadIdx.x;
    const int tx = t & 15;            // 16 n-groups of 8
    const int ty = t >> 4;            // 16 m-groups of 8
    const int rowBase = blockIdx.y * TM;
    const int colBase = blockIdx.x * TN;

    // staging coords: tile chunk = 128 rows x 4 float4
    const int m0  = t >> 2;           // row (0..63)
    const int m1  = m0 + 64;          // row (64..127)
    const int kq  = (t & 3) << 2;     // k quad within chunk

    float acc[8][8];
#pragma unroll
    for (int i = 0; i < 8; i++)
#pragma unroll
        for (int j = 0; j < 8; j++) acc[i][j] = 0.0f;

    float4 ar0, ar1, br0, br1;        // named regs: no arrays, no punning
    const int nChunks = DIMS / TK;    // 48

    // clamped source rows (reads only; writes are guarded in epilogue)
    int arow0 = rowBase + m0; if (arow0 > NQ - 1) arow0 = NQ - 1;
    int arow1 = rowBase + m1; if (arow1 > NQ - 1) arow1 = NQ - 1;
    int brow0 = colBase + m0; if (brow0 > Mdb - 1) brow0 = Mdb - 1;
    int brow1 = colBase + m1; if (brow1 > Mdb - 1) brow1 = Mdb - 1;
    const float* pa0 = A + (size_t)arow0 * DIMS + kq;
    const float* pa1 = A + (size_t)arow1 * DIMS + kq;
    const float* pb0 = B + (size_t)brow0 * DIMS + kq;
    const float* pb1 = B + (size_t)brow1 * DIMS + kq;

#define LOAD_CHUNK(c)                                            \
    do {                                                         \
        ar0 = *(const float4*)(pa0 + (c) * TK);                  \
        ar1 = *(const float4*)(pa1 + (c) * TK);                  \
        br0 = *(const float4*)(pb0 + (c) * TK);                  \
        br1 = *(const float4*)(pb1 + (c) * TK);                  \
    } while (0)

#define STAGE_CHUNK(buf)                                         \
    do {                                                         \
        As[buf][kq + 0][m0] = ar0.x;                             \
        As[buf][kq + 1][m0] = ar0.y;                             \
        As[buf][kq + 2][m0] = ar0.z;                             \
        As[buf][kq + 3][m0] = ar0.w;                             \
        As[buf][kq + 0][m1] = ar1.x;                             \
        As[buf][kq + 1][m1] = ar1.y;                             \
        As[buf][kq + 2][m1] = ar1.z;                             \
        As[buf][kq + 3][m1] = ar1.w;                             \
        Bs[buf][kq + 0][m0] = br0.x;                             \
        Bs[buf][kq + 1][m0] = br0.y;                             \
        Bs[buf][kq + 2][m0] = br0.z;                             \
        Bs[buf][kq + 3][m0] = br0.w;                             \
        Bs[buf][kq + 0][m1] = br1.x;                             \
        Bs[buf][kq + 1][m1] = br1.y;                             \
        Bs[buf][kq + 2][m1] = br1.z;                             \
        Bs[buf][kq + 3][m1] = br1.w;                             \
    } while (0)

    LOAD_CHUNK(0);
    STAGE_CHUNK(0);
    __syncthreads();

    for (int c = 0; c < nChunks; c++) {
        int buf = c & 1;
        if (c + 1 < nChunks) LOAD_CHUNK(c + 1);   // overlap LDG with compute

#pragma unroll
        for (int kk = 0; kk < TK; kk++) {
            float4 a0 = *(const float4*)&As[buf][kk][ty * 8];
            float4 a1 = *(const float4*)&As[buf][kk][ty * 8 + 4];
            float4 b0 = *(const float4*)&Bs[buf][kk][tx * 8];
            float4 b1 = *(const float4*)&Bs[buf][kk][tx * 8 + 4];
            float av[8], bv[8];
            av[0]=a0.x; av[1]=a0.y; av[2]=a0.z; av[3]=a0.w;
            av[4]=a1.x; av[5]=a1.y; av[6]=a1.z; av[7]=a1.w;
            bv[0]=b0.x; bv[1]=b0.y; bv[2]=b0.z; bv[3]=b0.w;
            bv[4]=b1.x; bv[5]=b1.y; bv[6]=b1.z; bv[7]=b1.w;
#pragma unroll
            for (int i = 0; i < 8; i++)
#pragma unroll
                for (int j = 0; j < 8; j++)
                    acc[i][j] = fmaf(av[i], bv[j], acc[i][j]);
        }

        if (c + 1 < nChunks) STAGE_CHUNK(buf ^ 1);
        __syncthreads();
    }

    // Epilogue: write raw dot products
    const int col0 = colBase + tx * 8;
    if (col0 + 7 < Mdb && rowBase + TM <= NQ) {
#pragma unroll
        for (int i = 0; i < 8; i++) {
            int row = rowBase + ty * 8 + i;
            float* p = g_scores + (size_t)row * Mdb + col0;
            *(float4*)(p)     = make_float4(acc[i][0], acc[i][1], acc[i][2], acc[i][3]);
            *(float4*)(p + 4) = make_float4(acc[i][4], acc[i][5], acc[i][6], acc[i][7]);
        }
    } else {
#pragma unroll
        for (int i = 0; i < 8; i++) {
            int row = rowBase + ty * 8 + i;
            if (row >= NQ) continue;
#pragma unroll
            for (int j = 0; j < 8; j++) {
                int col = col0 + j;
                if (col < Mdb)
                    g_scores[(size_t)row * Mdb + col] = acc[i][j];
            }
        }
    }
#undef LOAD_CHUNK
#undef STAGE_CHUNK
}

// ---------------------------------------------------------------------------
// Top-16 per query (UNCHANGED from passing R2 kernel).
// ---------------------------------------------------------------------------
__global__ void __launch_bounds__(512)
topk_kernel(float* __restrict__ out, int NQ, int Mdb)
{
    const int q    = blockIdx.x;
    const int t    = threadIdx.x;
    const int lane = t & 31;
    const int wid  = t >> 5;
    const float* row = g_scores + (size_t)q * Mdb;

    float val[16];
    int   idx[16];
#pragma unroll
    for (int i = 0; i < 16; i++) { val[i] = -FLT_MAX; idx[i] = 0x7fffffff; }
    float vmin = -FLT_MAX;

    auto consider = [&](float s, int j) {
        bool take = (s > vmin) || (s == vmin && j < idx[15]);
        if (take) {
            int p = 15;
            while (p > 0 && (val[p - 1] < s || (val[p - 1] == s && idx[p - 1] > j))) {
                val[p] = val[p - 1]; idx[p] = idx[p - 1]; --p;
            }
            val[p] = s; idx[p] = j;
            vmin = val[15];
        }
    };

    if ((Mdb & 3) == 0) {
        const float4* r4 = (const float4*)row;
        int nf4 = Mdb >> 2;
        for (int f = t; f < nf4; f += 512) {
            float4 v = r4[f];
            int j = f << 2;
            consider(v.x, j);
            consider(v.y, j + 1);
            consider(v.z, j + 2);
            consider(v.w, j + 3);
        }
    } else {
        for (int j = t; j < Mdb; j += 512) consider(row[j], j);
    }

    __shared__ float sv[16];
    __shared__ int   si[16];
    __shared__ int   st[16];
    __shared__ int   wt;

    int pos = 0;
    for (int r = 0; r < 16; r++) {
        float v  = (pos < 16) ? val[pos] : -FLT_MAX;
        int   ii = (pos < 16) ? idx[pos] : 0x7fffffff;
        int   tt = t;
#pragma unroll
        for (int o = 16; o; o >>= 1) {
            float v2 = __shfl_xor_sync(0xffffffffu, v, o);
            int   i2 = __shfl_xor_sync(0xffffffffu, ii, o);
            int   t2 = __shfl_xor_sync(0xffffffffu, tt, o);
            if (v2 > v || (v2 == v && i2 < ii)) { v = v2; ii = i2; tt = t2; }
        }
        if (lane == 0) { sv[wid] = v; si[wid] = ii; st[wid] = tt; }
        __syncthreads();
        if (t == 0) {
            float bv = sv[0]; int bi = si[0]; int bt = st[0];
#pragma unroll
            for (int w = 1; w < 16; w++)
                if (sv[w] > bv || (sv[w] == bv && si[w] < bi)) {
                    bv = sv[w]; bi = si[w]; bt = st[w];
                }
            wt = bt;
            out[q * 16 + r]           = bv;
            out[NQ * 16 + q * 16 + r] = (float)bi;
        }
        __syncthreads();
        if (t == wt) pos++;
    }
}

// ---------------------------------------------------------------------------
extern "C" void kernel_launch(void* const* d_in, const int* in_sizes, int n_in,
                              void* d_out, int out_size)
{
    const float* q  = (const float*)d_in[0];
    const float* db = (const float*)d_in[1];
    int NQ  = in_sizes[0] / DIMS;   // 256
    int Mdb = in_sizes[1] / DIMS;   // 500000
    if (NQ > MAX_N) NQ = MAX_N;
    if (Mdb > MAX_M) Mdb = MAX_M;
    float* out = (float*)d_out;

    normalize_kernel<<<(Mdb + 7) / 8, 256>>>(db, g_dbn, Mdb);
    normalize_kernel<<<(NQ + 7) / 8, 256>>>(q, g_qn, NQ);

    dim3 grid((Mdb + TN - 1) / TN, (NQ + TM - 1) / TM);
    gemm_kernel<<<grid, 256>>>(g_qn, g_dbn, NQ, Mdb);

    topk_kernel<<<NQ, 512>>>(out, NQ, Mdb);
}